// round 2
// baseline (speedup 1.0000x reference)
#include <cuda_runtime.h>
#include <cstdint>

#define NENT   200000
#define NRELC  1000
#define DIM    512
#define BATCH  2048
#define NEG    64
#define NROWS  4096     // 2*BATCH cluster rows
#define EPSF   1e-12f
#define GAMMA_C  12.0f
#define GAMMA2_C 1.0f

// ---------------- scratch (__device__ globals; no allocations allowed) ------
__device__ float g_clus[NROWS * DIM];   // concat(h_clu, t_clu)
__device__ float g_qh[BATCH * DIM];     // h_comb + rel
__device__ float g_sq[NROWS];           // ||clus_i||^2
__device__ int   g_rowmin[NROWS];       // float-as-int row minima (>=0 so int order == float order)
__device__ float g_intra[NROWS];
__device__ float g_par[NROWS];
__device__ float g_textd[BATCH];
__device__ float g_true[BATCH];
__device__ float g_neg[BATCH * NEG];
__device__ float g_hier;

// ---------------- init --------------------------------------------------
__global__ void k_init() {
    int i = blockIdx.x * blockDim.x + threadIdx.x;
    if (i < NROWS) g_rowmin[i] = 0x7f800000;   // +inf
}

// ---------------- per-row gathers + reductions ---------------------------
__global__ __launch_bounds__(128) void k_rows(
    const int* __restrict__ sample,
    const int* __restrict__ cassign,
    const int* __restrict__ passign,
    const float* __restrict__ relemb,
    const float* __restrict__ einit,
    const float* __restrict__ etext,
    const float* __restrict__ cemb,
    const float* __restrict__ pemb)
{
    int b = blockIdx.x;
    int tid = threadIdx.x;        // 128 threads, each owns one float4 (4 dims)

    int h = sample[b * 3 + 0];
    int r = sample[b * 3 + 1] % NRELC;
    int t = sample[b * 3 + 2];
    int hc = cassign[h], tc = cassign[t];
    int hp = passign[hc], tp = passign[tc];

    const float4* Ih = (const float4*)(einit + (size_t)h  * DIM);
    const float4* Xh = (const float4*)(etext + (size_t)h  * DIM);
    const float4* It = (const float4*)(einit + (size_t)t  * DIM);
    const float4* Xt = (const float4*)(etext + (size_t)t  * DIM);
    const float4* Rr = (const float4*)(relemb + (size_t)r * DIM);
    const float4* Ch = (const float4*)(cemb  + (size_t)hc * DIM);
    const float4* Ct = (const float4*)(cemb  + (size_t)tc * DIM);
    const float4* Ph = (const float4*)(pemb  + (size_t)hp * DIM);
    const float4* Pt = (const float4*)(pemb  + (size_t)tp * DIM);

    float4 ih = Ih[tid], xh = Xh[tid], it = It[tid], xt = Xt[tid];
    float4 rr = Rr[tid], ch = Ch[tid], ct = Ct[tid], ph = Ph[tid], pt = Pt[tid];

    float vals[9];
    #pragma unroll
    for (int v = 0; v < 9; v++) vals[v] = 0.0f;

    float4 q4, ch4 = ch, ct4 = ct;
    {
        float hi[4] = {ih.x, ih.y, ih.z, ih.w};
        float hx[4] = {xh.x, xh.y, xh.z, xh.w};
        float ti[4] = {it.x, it.y, it.z, it.w};
        float tx2[4] = {xt.x, xt.y, xt.z, xt.w};
        float rv[4] = {rr.x, rr.y, rr.z, rr.w};
        float cv[4] = {ch.x, ch.y, ch.z, ch.w};
        float cw[4] = {ct.x, ct.y, ct.z, ct.w};
        float pv[4] = {ph.x, ph.y, ph.z, ph.w};
        float pw[4] = {pt.x, pt.y, pt.z, pt.w};
        float qv[4];
        #pragma unroll
        for (int c = 0; c < 4; c++) {
            float hcomb = 0.5f * (hi[c] + hx[c]);
            float tcomb = 0.5f * (ti[c] + tx2[c]);
            float q = hcomb + rv[c];
            qv[c] = q;
            vals[0] += fabsf(q - tcomb);                 // true-score L1
            float dh = 0.5f * (hi[c] - hx[c]);           // h_comb - h_text
            vals[1] += dh * dh;
            float dt = 0.5f * (ti[c] - tx2[c]);
            vals[2] += dt * dt;
            float eh = hcomb - cv[c];  vals[3] += eh * eh;  // intra h
            float et = tcomb - cw[c];  vals[4] += et * et;  // intra t
            float fh = cv[c] - pv[c];  vals[5] += fh * fh;  // parent h
            float ft = cw[c] - pw[c];  vals[6] += ft * ft;  // parent t
            vals[7] += cv[c] * cv[c];                       // ||h_clu||^2
            vals[8] += cw[c] * cw[c];                       // ||t_clu||^2
        }
        q4 = make_float4(qv[0], qv[1], qv[2], qv[3]);
    }

    // stage outputs
    ((float4*)(g_qh + (size_t)b * DIM))[tid] = q4;
    ((float4*)(g_clus + (size_t)b * DIM))[tid] = ch4;
    ((float4*)(g_clus + (size_t)(BATCH + b) * DIM))[tid] = ct4;

    // deterministic block reduction of 9 partials
    #pragma unroll
    for (int o = 16; o > 0; o >>= 1)
        #pragma unroll
        for (int v = 0; v < 9; v++)
            vals[v] += __shfl_down_sync(0xffffffffu, vals[v], o);

    __shared__ float sm[4][9];
    int warp = tid >> 5, lane = tid & 31;
    if (lane == 0) {
        #pragma unroll
        for (int v = 0; v < 9; v++) sm[warp][v] = vals[v];
    }
    __syncthreads();
    if (tid == 0) {
        float s[9];
        #pragma unroll
        for (int v = 0; v < 9; v++)
            s[v] = sm[0][v] + sm[1][v] + sm[2][v] + sm[3][v];
        g_true[b]          = GAMMA_C - s[0];
        g_textd[b]         = sqrtf(s[1] + EPSF) + sqrtf(s[2] + EPSF);
        g_intra[b]         = sqrtf(s[3] + EPSF);
        g_intra[BATCH + b] = sqrtf(s[4] + EPSF);
        g_par[b]           = sqrtf(s[5] + EPSF);
        g_par[BATCH + b]   = sqrtf(s[6] + EPSF);
        g_sq[b]            = s[7];
        g_sq[BATCH + b]    = s[8];
    }
}

// ---------------- negative-sample L1 scores -------------------------------
__global__ __launch_bounds__(128) void k_neg(
    const int* __restrict__ negtails,
    const float* __restrict__ einit,
    const float* __restrict__ etext)
{
    int idx = blockIdx.x;              // b*64 + m
    int e = negtails[idx];
    int b = idx >> 6;
    int tid = threadIdx.x;

    float4 q = ((const float4*)(g_qh + (size_t)b * DIM))[tid];
    float4 a = __ldg(((const float4*)(einit + (size_t)e * DIM)) + tid);
    float4 x = __ldg(((const float4*)(etext + (size_t)e * DIM)) + tid);

    float s = fabsf(q.x - 0.5f * (a.x + x.x))
            + fabsf(q.y - 0.5f * (a.y + x.y))
            + fabsf(q.z - 0.5f * (a.z + x.z))
            + fabsf(q.w - 0.5f * (a.w + x.w));

    #pragma unroll
    for (int o = 16; o > 0; o >>= 1)
        s += __shfl_down_sync(0xffffffffu, s, o);

    __shared__ float sm[4];
    if ((tid & 31) == 0) sm[tid >> 5] = s;
    __syncthreads();
    if (tid == 0)
        g_neg[idx] = GAMMA_C - (sm[0] + sm[1] + sm[2] + sm[3]);
}

// ---------------- symmetric pairwise-L2 row minima -------------------------
// 128x128 output tile per block, 256 threads, 8x8 register micro-tile,
// upper-triangle blocks only (528 of 1024); each block updates row-min for
// both its row range (min over j) and col range (min over i) via symmetry.
__global__ __launch_bounds__(256) void k_pairwise()
{
    // triangular block mapping
    int id = blockIdx.x;
    int bi = 0, rem = id;
    #pragma unroll 1
    for (int k = 0; k < 32; k++) {
        int rl = 32 - k;
        if (rem < rl) { bi = k; break; }
        rem -= rl;
    }
    int bj = bi + rem;
    const int i0 = bi * 128, j0 = bj * 128;

    __shared__ float As[16][132];
    __shared__ float Bs[16][132];

    float acc[8][8];
    #pragma unroll
    for (int ui = 0; ui < 8; ui++)
        #pragma unroll
        for (int uj = 0; uj < 8; uj++) acc[ui][uj] = 0.0f;

    int tid = threadIdx.x;
    int tx = tid & 15, ty = tid >> 4;

    for (int k0 = 0; k0 < DIM; k0 += 16) {
        #pragma unroll
        for (int s = 0; s < 2; s++) {
            int l = tid + s * 256;
            int row = l >> 2;
            int kq = (l & 3) << 2;
            float4 va = *(const float4*)(&g_clus[(size_t)(i0 + row) * DIM + k0 + kq]);
            As[kq + 0][row] = va.x; As[kq + 1][row] = va.y;
            As[kq + 2][row] = va.z; As[kq + 3][row] = va.w;
            float4 vb = *(const float4*)(&g_clus[(size_t)(j0 + row) * DIM + k0 + kq]);
            Bs[kq + 0][row] = vb.x; Bs[kq + 1][row] = vb.y;
            Bs[kq + 2][row] = vb.z; Bs[kq + 3][row] = vb.w;
        }
        __syncthreads();
        #pragma unroll
        for (int k = 0; k < 16; k++) {
            float a[8], bv[8];
            #pragma unroll
            for (int u = 0; u < 8; u++) a[u] = As[k][ty * 8 + u];
            #pragma unroll
            for (int u = 0; u < 8; u++) bv[u] = Bs[k][tx * 8 + u];
            #pragma unroll
            for (int ui = 0; ui < 8; ui++)
                #pragma unroll
                for (int uj = 0; uj < 8; uj++)
                    acc[ui][uj] = fmaf(a[ui], bv[uj], acc[ui][uj]);
        }
        __syncthreads();
    }

    __shared__ int srow[128], scol[128];
    if (tid < 128) { srow[tid] = 0x7f800000; scol[tid] = 0x7f800000; }
    __syncthreads();

    float si[8], sj[8];
    #pragma unroll
    for (int u = 0; u < 8; u++) {
        si[u] = g_sq[i0 + ty * 8 + u];
        sj[u] = g_sq[j0 + tx * 8 + u];
    }

    float rmin[8], cmin[8];
    #pragma unroll
    for (int u = 0; u < 8; u++) { rmin[u] = 1e30f; cmin[u] = 1e30f; }

    #pragma unroll
    for (int ui = 0; ui < 8; ui++) {
        int gi = i0 + ty * 8 + ui;
        #pragma unroll
        for (int uj = 0; uj < 8; uj++) {
            int gj = j0 + tx * 8 + uj;
            float d2 = si[ui] + sj[uj] - 2.0f * acc[ui][uj];
            float dd = sqrtf(fmaxf(d2, EPSF));
            if (gi != gj) {
                rmin[ui] = fminf(rmin[ui], dd);
                cmin[uj] = fminf(cmin[uj], dd);
            }
        }
    }

    #pragma unroll
    for (int u = 0; u < 8; u++) {
        atomicMin(&srow[ty * 8 + u], __float_as_int(rmin[u]));
        atomicMin(&scol[tx * 8 + u], __float_as_int(cmin[u]));
    }
    __syncthreads();
    if (tid < 128) {
        atomicMin(&g_rowmin[i0 + tid], srow[tid]);
        atomicMin(&g_rowmin[j0 + tid], scol[tid]);   // symmetric update (idempotent on diag)
    }
}

// ---------------- scalar loss reduction ------------------------------------
__global__ __launch_bounds__(1024) void k_reduce()
{
    int tid = threadIdx.x;
    float smin = 0.0f, sin_ = 0.0f, sp = 0.0f;
    for (int i = tid; i < NROWS; i += 1024) {
        smin += __int_as_float(g_rowmin[i]);
        sin_ += g_intra[i];
        sp   += g_par[i];
    }
    #pragma unroll
    for (int o = 16; o > 0; o >>= 1) {
        smin += __shfl_down_sync(0xffffffffu, smin, o);
        sin_ += __shfl_down_sync(0xffffffffu, sin_, o);
        sp   += __shfl_down_sync(0xffffffffu, sp,   o);
    }
    __shared__ float sm[32][3];
    int warp = tid >> 5, lane = tid & 31;
    if (lane == 0) { sm[warp][0] = smin; sm[warp][1] = sin_; sm[warp][2] = sp; }
    __syncthreads();
    if (warp == 0) {
        float a = (lane < 32) ? sm[lane][0] : 0.0f;
        float b = (lane < 32) ? sm[lane][1] : 0.0f;
        float c = (lane < 32) ? sm[lane][2] : 0.0f;
        #pragma unroll
        for (int o = 16; o > 0; o >>= 1) {
            a += __shfl_down_sync(0xffffffffu, a, o);
            b += __shfl_down_sync(0xffffffffu, b, o);
            c += __shfl_down_sync(0xffffffffu, c, o);
        }
        if (lane == 0)
            g_hier = (b - a + c) * (1.0f / (float)NROWS);  // intra - inter + parent (LAM1=LAM2=1)
    }
}

// ---------------- finalize ---------------------------------------------------
__global__ void k_final(float* __restrict__ out)
{
    int b = blockIdx.x * blockDim.x + threadIdx.x;
    if (b >= BATCH) return;
    float ns = 0.0f;
    const float* p = g_neg + (size_t)b * NEG;
    #pragma unroll
    for (int m = 0; m < NEG; m++) ns += p[m];
    float score = -0.5f * g_hier - 0.5f * g_textd[b]
                - GAMMA2_C * (g_true[b] - ns * (1.0f / (float)NEG));
    out[b] = score;
}

// ---------------- launch ------------------------------------------------------
extern "C" void kernel_launch(void* const* d_in, const int* in_sizes, int n_in,
                              void* d_out, int out_size)
{
    const int*   sample   = (const int*)d_in[0];
    const int*   negtails = (const int*)d_in[1];
    const int*   cassign  = (const int*)d_in[2];
    const int*   passign  = (const int*)d_in[3];
    const float* relemb   = (const float*)d_in[4];
    const float* einit    = (const float*)d_in[5];
    const float* etext    = (const float*)d_in[6];
    const float* cemb     = (const float*)d_in[7];
    const float* pemb     = (const float*)d_in[8];
    float* out = (float*)d_out;

    k_init<<<16, 256>>>();
    k_rows<<<BATCH, 128>>>(sample, cassign, passign, relemb, einit, etext, cemb, pemb);
    k_neg<<<BATCH * NEG, 128>>>(negtails, einit, etext);
    k_pairwise<<<528, 256>>>();
    k_reduce<<<1, 1024>>>();
    k_final<<<8, 256>>>(out);
}

// round 5
// speedup vs baseline: 1.3547x; 1.3547x over previous
#include <cuda_runtime.h>
#include <cuda_bf16.h>
#include <cstdint>

#define NENT   200000
#define NRELC  1000
#define DIM    512
#define BATCH  2048
#define NEG    64
#define NROWS  4096
#define EPSF   1e-12f
#define GAMMA_C  12.0f
#define GAMMA2_C 1.0f

// ---------------- scratch ----------------------------------------------------
__device__ __nv_bfloat16 g_clus_h[NROWS * DIM];   // hi part of cluster rows
__device__ __nv_bfloat16 g_clus_l[NROWS * DIM];   // lo part
__device__ float g_qh[BATCH * DIM];
__device__ float g_sq[NROWS];
__device__ int   g_rowmin[NROWS];
__device__ float g_intra[NROWS];
__device__ float g_par[NROWS];
__device__ float g_textd[BATCH];
__device__ float g_true[BATCH];
__device__ float g_neg[BATCH * NEG];
__device__ float g_hier;

__device__ __forceinline__ uint32_t smem_u32(const void* p) {
    uint32_t a;
    asm("{ .reg .u64 t; cvta.to.shared.u64 t, %1; cvt.u32.u64 %0, t; }" : "=r"(a) : "l"(p));
    return a;
}

#define LDSM_X4(r0, r1, r2, r3, addr) \
    asm volatile("ldmatrix.sync.aligned.m8n8.x4.shared.b16 {%0,%1,%2,%3}, [%4];" \
        : "=r"(r0), "=r"(r1), "=r"(r2), "=r"(r3) : "r"(addr))

#define MMA_BF16(c, a, b0, b1) \
    asm volatile("mma.sync.aligned.m16n8k16.row.col.f32.bf16.bf16.f32 " \
        "{%0,%1,%2,%3}, {%4,%5,%6,%7}, {%8,%9}, {%0,%1,%2,%3};" \
        : "+f"((c)[0]), "+f"((c)[1]), "+f"((c)[2]), "+f"((c)[3]) \
        : "r"((a)[0]), "r"((a)[1]), "r"((a)[2]), "r"((a)[3]), "r"(b0), "r"(b1))

// ---------------- init -------------------------------------------------------
__global__ void k_init() {
    int i = blockIdx.x * blockDim.x + threadIdx.x;
    if (i < NROWS) g_rowmin[i] = 0x7f800000;
}

// ---------------- per-row gathers + reductions -------------------------------
__device__ __forceinline__ void split_store(int row, int tid, float4 v) {
    union { __nv_bfloat16 b[4]; uint2 u; } uh, ul;
    float xs[4] = {v.x, v.y, v.z, v.w};
    #pragma unroll
    for (int c = 0; c < 4; c++) {
        __nv_bfloat16 h = __float2bfloat16(xs[c]);
        uh.b[c] = h;
        ul.b[c] = __float2bfloat16(xs[c] - __bfloat162float(h));
    }
    *(uint2*)(g_clus_h + (size_t)row * DIM + tid * 4) = uh.u;
    *(uint2*)(g_clus_l + (size_t)row * DIM + tid * 4) = ul.u;
}

__global__ __launch_bounds__(128) void k_rows(
    const int* __restrict__ sample,
    const int* __restrict__ cassign,
    const int* __restrict__ passign,
    const float* __restrict__ relemb,
    const float* __restrict__ einit,
    const float* __restrict__ etext,
    const float* __restrict__ cemb,
    const float* __restrict__ pemb)
{
    int b = blockIdx.x;
    int tid = threadIdx.x;

    int h = sample[b * 3 + 0];
    int r = sample[b * 3 + 1] % NRELC;
    int t = sample[b * 3 + 2];
    int hc = cassign[h], tc = cassign[t];
    int hp = passign[hc], tp = passign[tc];

    float4 ih = ((const float4*)(einit + (size_t)h  * DIM))[tid];
    float4 xh = ((const float4*)(etext + (size_t)h  * DIM))[tid];
    float4 it = ((const float4*)(einit + (size_t)t  * DIM))[tid];
    float4 xt = ((const float4*)(etext + (size_t)t  * DIM))[tid];
    float4 rr = ((const float4*)(relemb + (size_t)r * DIM))[tid];
    float4 ch = ((const float4*)(cemb  + (size_t)hc * DIM))[tid];
    float4 ct = ((const float4*)(cemb  + (size_t)tc * DIM))[tid];
    float4 ph = ((const float4*)(pemb  + (size_t)hp * DIM))[tid];
    float4 pt = ((const float4*)(pemb  + (size_t)tp * DIM))[tid];

    float vals[9];
    #pragma unroll
    for (int v = 0; v < 9; v++) vals[v] = 0.0f;

    float4 q4;
    {
        float hi[4] = {ih.x, ih.y, ih.z, ih.w};
        float hx[4] = {xh.x, xh.y, xh.z, xh.w};
        float ti[4] = {it.x, it.y, it.z, it.w};
        float tx2[4] = {xt.x, xt.y, xt.z, xt.w};
        float rv[4] = {rr.x, rr.y, rr.z, rr.w};
        float cv[4] = {ch.x, ch.y, ch.z, ch.w};
        float cw[4] = {ct.x, ct.y, ct.z, ct.w};
        float pv[4] = {ph.x, ph.y, ph.z, ph.w};
        float pw[4] = {pt.x, pt.y, pt.z, pt.w};
        float qv[4];
        #pragma unroll
        for (int c = 0; c < 4; c++) {
            float hcomb = 0.5f * (hi[c] + hx[c]);
            float tcomb = 0.5f * (ti[c] + tx2[c]);
            float q = hcomb + rv[c];
            qv[c] = q;
            vals[0] += fabsf(q - tcomb);
            float dh = 0.5f * (hi[c] - hx[c]);  vals[1] += dh * dh;
            float dt = 0.5f * (ti[c] - tx2[c]); vals[2] += dt * dt;
            float eh = hcomb - cv[c];  vals[3] += eh * eh;
            float et = tcomb - cw[c];  vals[4] += et * et;
            float fh = cv[c] - pv[c];  vals[5] += fh * fh;
            float ft = cw[c] - pw[c];  vals[6] += ft * ft;
            vals[7] += cv[c] * cv[c];
            vals[8] += cw[c] * cw[c];
        }
        q4 = make_float4(qv[0], qv[1], qv[2], qv[3]);
    }

    ((float4*)(g_qh + (size_t)b * DIM))[tid] = q4;
    split_store(b,         tid, ch);
    split_store(BATCH + b, tid, ct);

    #pragma unroll
    for (int o = 16; o > 0; o >>= 1)
        #pragma unroll
        for (int v = 0; v < 9; v++)
            vals[v] += __shfl_down_sync(0xffffffffu, vals[v], o);

    __shared__ float sm[4][9];
    int warp = tid >> 5, lane = tid & 31;
    if (lane == 0) {
        #pragma unroll
        for (int v = 0; v < 9; v++) sm[warp][v] = vals[v];
    }
    __syncthreads();
    if (tid == 0) {
        float s[9];
        #pragma unroll
        for (int v = 0; v < 9; v++)
            s[v] = sm[0][v] + sm[1][v] + sm[2][v] + sm[3][v];
        g_true[b]          = GAMMA_C - s[0];
        g_textd[b]         = sqrtf(s[1] + EPSF) + sqrtf(s[2] + EPSF);
        g_intra[b]         = sqrtf(s[3] + EPSF);
        g_intra[BATCH + b] = sqrtf(s[4] + EPSF);
        g_par[b]           = sqrtf(s[5] + EPSF);
        g_par[BATCH + b]   = sqrtf(s[6] + EPSF);
        g_sq[b]            = s[7];
        g_sq[BATCH + b]    = s[8];
    }
}

// ---------------- negative-sample L1 scores ----------------------------------
__global__ __launch_bounds__(128) void k_neg(
    const int* __restrict__ negtails,
    const float* __restrict__ einit,
    const float* __restrict__ etext)
{
    int idx = blockIdx.x;
    int e = negtails[idx];
    int b = idx >> 6;
    int tid = threadIdx.x;

    float4 q = ((const float4*)(g_qh + (size_t)b * DIM))[tid];
    float4 a = __ldg(((const float4*)(einit + (size_t)e * DIM)) + tid);
    float4 x = __ldg(((const float4*)(etext + (size_t)e * DIM)) + tid);

    float s = fabsf(q.x - 0.5f * (a.x + x.x))
            + fabsf(q.y - 0.5f * (a.y + x.y))
            + fabsf(q.z - 0.5f * (a.z + x.z))
            + fabsf(q.w - 0.5f * (a.w + x.w));

    #pragma unroll
    for (int o = 16; o > 0; o >>= 1)
        s += __shfl_down_sync(0xffffffffu, s, o);

    __shared__ float sm[4];
    if ((tid & 31) == 0) sm[tid >> 5] = s;
    __syncthreads();
    if (tid == 0)
        g_neg[idx] = GAMMA_C - (sm[0] + sm[1] + sm[2] + sm[3]);
}

// ---------------- mma.sync pairwise-L2 row minima ----------------------------
// 128x128 tile/CTA, 8 warps of 32x64, bf16 split (hi/lo): dot = hh + lh + hl
// accumulated in one fp32 mma accumulator. K chunked by 32, ldmatrix operands.
#define KC   32
#define LDT  40        // padded smem row stride (bf16 elems)

__global__ __launch_bounds__(256) void k_pairwise()
{
    __shared__ __align__(16) __nv_bfloat16 sAh[128 * LDT], sAl[128 * LDT];
    __shared__ __align__(16) __nv_bfloat16 sBh[128 * LDT], sBl[128 * LDT];
    __shared__ float ssq[128];
    __shared__ int srow[128], scol[128];

    int tid = threadIdx.x, lane = tid & 31, wid = tid >> 5;

    // triangular block mapping
    int id = blockIdx.x;
    int bi = 0, rem = id;
    #pragma unroll 1
    for (int k = 0; k < 32; k++) {
        int rl = 32 - k;
        if (rem < rl) { bi = k; break; }
        rem -= rl;
    }
    int bj = bi + rem;
    const int i0 = bi * 128, j0 = bj * 128;
    const bool diag = (i0 == j0);

    if (tid < 128) {
        srow[tid] = 0x7f800000; scol[tid] = 0x7f800000;
        ssq[tid] = g_sq[j0 + tid];
    }

    const int warpRow = (wid & 3) * 32;
    const int warpCol = (wid >> 2) * 64;

    float c[2][8][4];
    #pragma unroll
    for (int mi = 0; mi < 2; mi++)
        #pragma unroll
        for (int nj = 0; nj < 8; nj++)
            #pragma unroll
            for (int q = 0; q < 4; q++) c[mi][nj][q] = 0.0f;

    // ldmatrix lane->row/col mapping
    // A x4 blocks: {r+0,k+0},{r+8,k+0},{r+0,k+8},{r+8,k+8}
    int aRow = warpRow + (lane & 7) + ((lane >> 3) & 1) * 8;
    int aCol = (lane >> 4) * 8;
    // B x4 blocks (covers 2 n8 tiles): {n+0,k+0},{n+0,k+8},{n+8,k+0},{n+8,k+8}
    int bRow = warpCol + (lane & 7) + (lane >> 4) * 8;
    int bCol = ((lane >> 3) & 1) * 8;

    uint32_t baseAh = smem_u32(sAh), baseAl = smem_u32(sAl);
    uint32_t baseBh = smem_u32(sBh), baseBl = smem_u32(sBl);

    const __nv_bfloat16* gAh = g_clus_h + (size_t)i0 * DIM;
    const __nv_bfloat16* gAl = g_clus_l + (size_t)i0 * DIM;
    const __nv_bfloat16* gBh = g_clus_h + (size_t)j0 * DIM;
    const __nv_bfloat16* gBl = g_clus_l + (size_t)j0 * DIM;

    for (int kc = 0; kc < DIM; kc += KC) {
        __syncthreads();   // previous compute done before overwriting smem
        // stage 4 tiles of 128 rows x 32 bf16 (4 uint4 per row)
        #pragma unroll
        for (int it = 0; it < 2; it++) {
            int idx = it * 256 + tid;          // 0..511
            int row = idx >> 2, q = idx & 3;
            uint32_t so = row * LDT + q * 8;
            size_t  go = (size_t)row * DIM + kc + q * 8;
            *(uint4*)(sAh + so) = *(const uint4*)(gAh + go);
            *(uint4*)(sAl + so) = *(const uint4*)(gAl + go);
            *(uint4*)(sBh + so) = *(const uint4*)(gBh + go);
            *(uint4*)(sBl + so) = *(const uint4*)(gBl + go);
        }
        __syncthreads();

        #pragma unroll
        for (int ks = 0; ks < KC; ks += 16) {
            uint32_t ah[2][4], al[2][4], b[4][4];
            #pragma unroll
            for (int mi = 0; mi < 2; mi++) {
                uint32_t addr = baseAh + ((aRow + mi * 16) * LDT + aCol + ks) * 2;
                LDSM_X4(ah[mi][0], ah[mi][1], ah[mi][2], ah[mi][3], addr);
                addr = baseAl + ((aRow + mi * 16) * LDT + aCol + ks) * 2;
                LDSM_X4(al[mi][0], al[mi][1], al[mi][2], al[mi][3], addr);
            }
            // Bh fragments -> hh + lh
            #pragma unroll
            for (int pj = 0; pj < 4; pj++) {
                uint32_t addr = baseBh + ((bRow + pj * 16) * LDT + bCol + ks) * 2;
                LDSM_X4(b[pj][0], b[pj][1], b[pj][2], b[pj][3], addr);
            }
            #pragma unroll
            for (int mi = 0; mi < 2; mi++)
                #pragma unroll
                for (int nj = 0; nj < 8; nj++) {
                    int pj = nj >> 1, hh = (nj & 1) * 2;
                    MMA_BF16(c[mi][nj], ah[mi], b[pj][hh], b[pj][hh + 1]);
                    MMA_BF16(c[mi][nj], al[mi], b[pj][hh], b[pj][hh + 1]);
                }
            // Bl fragments -> hl
            #pragma unroll
            for (int pj = 0; pj < 4; pj++) {
                uint32_t addr = baseBl + ((bRow + pj * 16) * LDT + bCol + ks) * 2;
                LDSM_X4(b[pj][0], b[pj][1], b[pj][2], b[pj][3], addr);
            }
            #pragma unroll
            for (int mi = 0; mi < 2; mi++)
                #pragma unroll
                for (int nj = 0; nj < 8; nj++) {
                    int pj = nj >> 1, hh = (nj & 1) * 2;
                    MMA_BF16(c[mi][nj], ah[mi], b[pj][hh], b[pj][hh + 1]);
                }
        }
    }
    __syncthreads();

    // epilogue: c-frag mapping: c0/c1 row=lane/4, cols 2*(lane%4)+{0,1}; c2/c3 row+8
    int tq = lane >> 2, tr = lane & 3;
    float cmin[8][2];
    #pragma unroll
    for (int nj = 0; nj < 8; nj++) { cmin[nj][0] = 1e30f; cmin[nj][1] = 1e30f; }

    #pragma unroll
    for (int mi = 0; mi < 2; mi++) {
        #pragma unroll
        for (int hr = 0; hr < 2; hr++) {
            int rl = warpRow + mi * 16 + hr * 8 + tq;
            float si = g_sq[i0 + rl];
            float rmin = 1e30f;
            #pragma unroll
            for (int nj = 0; nj < 8; nj++) {
                #pragma unroll
                for (int cc = 0; cc < 2; cc++) {
                    int cl = warpCol + nj * 8 + tr * 2 + cc;
                    float d2 = si + ssq[cl] - 2.0f * c[mi][nj][hr * 2 + cc];
                    float d = sqrtf(fmaxf(d2, EPSF));
                    if (diag && rl == cl) d = 1e30f;
                    rmin = fminf(rmin, d);
                    cmin[nj][cc] = fminf(cmin[nj][cc], d);
                }
            }
            rmin = fminf(rmin, __shfl_xor_sync(0xffffffffu, rmin, 1));
            rmin = fminf(rmin, __shfl_xor_sync(0xffffffffu, rmin, 2));
            if (tr == 0) atomicMin(&srow[rl], __float_as_int(rmin));
        }
    }
    #pragma unroll
    for (int nj = 0; nj < 8; nj++)
        #pragma unroll
        for (int cc = 0; cc < 2; cc++) {
            float v = cmin[nj][cc];
            v = fminf(v, __shfl_xor_sync(0xffffffffu, v, 4));
            v = fminf(v, __shfl_xor_sync(0xffffffffu, v, 8));
            v = fminf(v, __shfl_xor_sync(0xffffffffu, v, 16));
            if (tq == 0)
                atomicMin(&scol[warpCol + nj * 8 + tr * 2 + cc], __float_as_int(v));
        }
    __syncthreads();

    if (tid < 128) {
        atomicMin(&g_rowmin[i0 + tid], srow[tid]);
        atomicMin(&g_rowmin[j0 + tid], scol[tid]);
    }
}

// ---------------- scalar loss reduction --------------------------------------
__global__ __launch_bounds__(1024) void k_reduce()
{
    int tid = threadIdx.x;
    float smin = 0.0f, sin_ = 0.0f, sp = 0.0f;
    for (int i = tid; i < NROWS; i += 1024) {
        smin += __int_as_float(g_rowmin[i]);
        sin_ += g_intra[i];
        sp   += g_par[i];
    }
    #pragma unroll
    for (int o = 16; o > 0; o >>= 1) {
        smin += __shfl_down_sync(0xffffffffu, smin, o);
        sin_ += __shfl_down_sync(0xffffffffu, sin_, o);
        sp   += __shfl_down_sync(0xffffffffu, sp,   o);
    }
    __shared__ float sm[32][3];
    int warp = tid >> 5, lane = tid & 31;
    if (lane == 0) { sm[warp][0] = smin; sm[warp][1] = sin_; sm[warp][2] = sp; }
    __syncthreads();
    if (warp == 0) {
        float a = sm[lane][0], b = sm[lane][1], c = sm[lane][2];
        #pragma unroll
        for (int o = 16; o > 0; o >>= 1) {
            a += __shfl_down_sync(0xffffffffu, a, o);
            b += __shfl_down_sync(0xffffffffu, b, o);
            c += __shfl_down_sync(0xffffffffu, c, o);
        }
        if (lane == 0)
            g_hier = (b - a + c) * (1.0f / (float)NROWS);
    }
}

// ---------------- finalize ----------------------------------------------------
__global__ void k_final(float* __restrict__ out)
{
    int b = blockIdx.x * blockDim.x + threadIdx.x;
    if (b >= BATCH) return;
    float ns = 0.0f;
    const float* p = g_neg + (size_t)b * NEG;
    #pragma unroll
    for (int m = 0; m < NEG; m++) ns += p[m];
    out[b] = -0.5f * g_hier - 0.5f * g_textd[b]
           - GAMMA2_C * (g_true[b] - ns * (1.0f / (float)NEG));
}

// ---------------- launch ------------------------------------------------------
extern "C" void kernel_launch(void* const* d_in, const int* in_sizes, int n_in,
                              void* d_out, int out_size)
{
    const int*   sample   = (const int*)d_in[0];
    const int*   negtails = (const int*)d_in[1];
    const int*   cassign  = (const int*)d_in[2];
    const int*   passign  = (const int*)d_in[3];
    const float* relemb   = (const float*)d_in[4];
    const float* einit    = (const float*)d_in[5];
    const float* etext    = (const float*)d_in[6];
    const float* cemb     = (const float*)d_in[7];
    const float* pemb     = (const float*)d_in[8];
    float* out = (float*)d_out;

    k_init<<<16, 256>>>();
    k_rows<<<BATCH, 128>>>(sample, cassign, passign, relemb, einit, etext, cemb, pemb);
    k_neg<<<BATCH * NEG, 128>>>(negtails, einit, etext);
    k_pairwise<<<528, 256>>>();
    k_reduce<<<1, 1024>>>();
    k_final<<<8, 256>>>(out);
}

// round 6
// speedup vs baseline: 1.7420x; 1.2859x over previous
#include <cuda_runtime.h>
#include <cuda_bf16.h>
#include <cstdint>

#define NENT   200000
#define NRELC  1000
#define DIM    512
#define BATCH  2048
#define NEG    64
#define NROWS  4096
#define EPSF   1e-12f
#define GAMMA_C  12.0f
#define GAMMA2_C 1.0f

// ---------------- scratch ----------------------------------------------------
__device__ __nv_bfloat16 g_clus_h[NROWS * DIM];
__device__ __nv_bfloat16 g_clus_l[NROWS * DIM];
__device__ float g_qh[BATCH * DIM];
__device__ float g_sq[NROWS];
__device__ int   g_rowmin[NROWS];
__device__ float g_intra[NROWS];
__device__ float g_par[NROWS];
__device__ float g_textd[BATCH];
__device__ float g_true[BATCH];
__device__ float g_neg[BATCH * NEG];
__device__ float g_hier;

__device__ __forceinline__ uint32_t smem_u32(const void* p) {
    uint32_t a;
    asm("{ .reg .u64 t; cvta.to.shared.u64 t, %1; cvt.u32.u64 %0, t; }" : "=r"(a) : "l"(p));
    return a;
}

#define LDSM_X4(r0, r1, r2, r3, addr) \
    asm volatile("ldmatrix.sync.aligned.m8n8.x4.shared.b16 {%0,%1,%2,%3}, [%4];" \
        : "=r"(r0), "=r"(r1), "=r"(r2), "=r"(r3) : "r"(addr))

#define MMA_BF16(c, a, b0, b1) \
    asm volatile("mma.sync.aligned.m16n8k16.row.col.f32.bf16.bf16.f32 " \
        "{%0,%1,%2,%3}, {%4,%5,%6,%7}, {%8,%9}, {%0,%1,%2,%3};" \
        : "+f"((c)[0]), "+f"((c)[1]), "+f"((c)[2]), "+f"((c)[3]) \
        : "r"((a)[0]), "r"((a)[1]), "r"((a)[2]), "r"((a)[3]), "r"(b0), "r"(b1))

#define CP_ASYNC16(dst, src) \
    asm volatile("cp.async.cg.shared.global [%0], [%1], 16;" :: "r"(dst), "l"(src))
#define CP_COMMIT() asm volatile("cp.async.commit_group;" ::: "memory")
#define CP_WAIT(n)  asm volatile("cp.async.wait_group %0;" :: "n"(n) : "memory")

// ---------------- per-row gathers + reductions -------------------------------
__device__ __forceinline__ void split_store(int row, int tid, float4 v) {
    union { __nv_bfloat16 b[4]; uint2 u; } uh, ul;
    float xs[4] = {v.x, v.y, v.z, v.w};
    #pragma unroll
    for (int c = 0; c < 4; c++) {
        __nv_bfloat16 h = __float2bfloat16(xs[c]);
        uh.b[c] = h;
        ul.b[c] = __float2bfloat16(xs[c] - __bfloat162float(h));
    }
    *(uint2*)(g_clus_h + (size_t)row * DIM + tid * 4) = uh.u;
    *(uint2*)(g_clus_l + (size_t)row * DIM + tid * 4) = ul.u;
}

__global__ __launch_bounds__(128) void k_rows(
    const int* __restrict__ sample,
    const int* __restrict__ cassign,
    const int* __restrict__ passign,
    const float* __restrict__ relemb,
    const float* __restrict__ einit,
    const float* __restrict__ etext,
    const float* __restrict__ cemb,
    const float* __restrict__ pemb)
{
    int b = blockIdx.x;
    int tid = threadIdx.x;

    if (tid == 0) {                       // init row minima (replaces k_init)
        g_rowmin[b] = 0x7f800000;
        g_rowmin[BATCH + b] = 0x7f800000;
    }

    int h = sample[b * 3 + 0];
    int r = sample[b * 3 + 1] % NRELC;
    int t = sample[b * 3 + 2];
    int hc = cassign[h], tc = cassign[t];
    int hp = passign[hc], tp = passign[tc];

    float4 ih = ((const float4*)(einit + (size_t)h  * DIM))[tid];
    float4 xh = ((const float4*)(etext + (size_t)h  * DIM))[tid];
    float4 it = ((const float4*)(einit + (size_t)t  * DIM))[tid];
    float4 xt = ((const float4*)(etext + (size_t)t  * DIM))[tid];
    float4 rr = ((const float4*)(relemb + (size_t)r * DIM))[tid];
    float4 ch = ((const float4*)(cemb  + (size_t)hc * DIM))[tid];
    float4 ct = ((const float4*)(cemb  + (size_t)tc * DIM))[tid];
    float4 ph = ((const float4*)(pemb  + (size_t)hp * DIM))[tid];
    float4 pt = ((const float4*)(pemb  + (size_t)tp * DIM))[tid];

    float vals[9];
    #pragma unroll
    for (int v = 0; v < 9; v++) vals[v] = 0.0f;

    float4 q4;
    {
        float hi[4] = {ih.x, ih.y, ih.z, ih.w};
        float hx[4] = {xh.x, xh.y, xh.z, xh.w};
        float ti[4] = {it.x, it.y, it.z, it.w};
        float tx2[4] = {xt.x, xt.y, xt.z, xt.w};
        float rv[4] = {rr.x, rr.y, rr.z, rr.w};
        float cv[4] = {ch.x, ch.y, ch.z, ch.w};
        float cw[4] = {ct.x, ct.y, ct.z, ct.w};
        float pv[4] = {ph.x, ph.y, ph.z, ph.w};
        float pw[4] = {pt.x, pt.y, pt.z, pt.w};
        float qv[4];
        #pragma unroll
        for (int c = 0; c < 4; c++) {
            float hcomb = 0.5f * (hi[c] + hx[c]);
            float tcomb = 0.5f * (ti[c] + tx2[c]);
            float q = hcomb + rv[c];
            qv[c] = q;
            vals[0] += fabsf(q - tcomb);
            float dh = 0.5f * (hi[c] - hx[c]);  vals[1] += dh * dh;
            float dt = 0.5f * (ti[c] - tx2[c]); vals[2] += dt * dt;
            float eh = hcomb - cv[c];  vals[3] += eh * eh;
            float et = tcomb - cw[c];  vals[4] += et * et;
            float fh = cv[c] - pv[c];  vals[5] += fh * fh;
            float ft = cw[c] - pw[c];  vals[6] += ft * ft;
            vals[7] += cv[c] * cv[c];
            vals[8] += cw[c] * cw[c];
        }
        q4 = make_float4(qv[0], qv[1], qv[2], qv[3]);
    }

    ((float4*)(g_qh + (size_t)b * DIM))[tid] = q4;
    split_store(b,         tid, ch);
    split_store(BATCH + b, tid, ct);

    #pragma unroll
    for (int o = 16; o > 0; o >>= 1)
        #pragma unroll
        for (int v = 0; v < 9; v++)
            vals[v] += __shfl_down_sync(0xffffffffu, vals[v], o);

    __shared__ float sm[4][9];
    int warp = tid >> 5, lane = tid & 31;
    if (lane == 0) {
        #pragma unroll
        for (int v = 0; v < 9; v++) sm[warp][v] = vals[v];
    }
    __syncthreads();
    if (tid == 0) {
        float s[9];
        #pragma unroll
        for (int v = 0; v < 9; v++)
            s[v] = sm[0][v] + sm[1][v] + sm[2][v] + sm[3][v];
        g_true[b]          = GAMMA_C - s[0];
        g_textd[b]         = sqrtf(s[1] + EPSF) + sqrtf(s[2] + EPSF);
        g_intra[b]         = sqrtf(s[3] + EPSF);
        g_intra[BATCH + b] = sqrtf(s[4] + EPSF);
        g_par[b]           = sqrtf(s[5] + EPSF);
        g_par[BATCH + b]   = sqrtf(s[6] + EPSF);
        g_sq[b]            = s[7];
        g_sq[BATCH + b]    = s[8];
    }
}

// ---------------- negative-sample L1 scores ----------------------------------
// One block per b. q staged in smem once; each warp owns 8 negs, lane loops
// 4x float4 per array. No per-iteration barriers; coalesced 512B warp loads.
__global__ __launch_bounds__(256) void k_neg(
    const int* __restrict__ negtails,
    const float* __restrict__ einit,
    const float* __restrict__ etext)
{
    int b = blockIdx.x;
    int tid = threadIdx.x;
    __shared__ __align__(16) float qs[DIM];

    ((float2*)qs)[tid] = ((const float2*)(g_qh + (size_t)b * DIM))[tid];
    __syncthreads();

    int w = tid >> 5, lane = tid & 31;
    const float4* qv = (const float4*)qs;

    #pragma unroll 1
    for (int mm = 0; mm < 8; mm++) {
        int m = w * 8 + mm;
        int e = negtails[b * NEG + m];
        const float4* av = (const float4*)(einit + (size_t)e * DIM);
        const float4* xv = (const float4*)(etext + (size_t)e * DIM);
        float s = 0.0f;
        #pragma unroll
        for (int i = 0; i < 4; i++) {
            int idx = i * 32 + lane;
            float4 a = __ldg(av + idx);
            float4 x = __ldg(xv + idx);
            float4 q = qv[idx];
            s += fabsf(q.x - 0.5f * (a.x + x.x))
               + fabsf(q.y - 0.5f * (a.y + x.y))
               + fabsf(q.z - 0.5f * (a.z + x.z))
               + fabsf(q.w - 0.5f * (a.w + x.w));
        }
        #pragma unroll
        for (int o = 16; o > 0; o >>= 1)
            s += __shfl_down_sync(0xffffffffu, s, o);
        if (lane == 0)
            g_neg[b * NEG + m] = GAMMA_C - s;
    }
}

// ---------------- mma.sync pairwise-L2 row minima ----------------------------
// 128x128 tile/CTA, 8 warps of 32x64, bf16 split: dot = hh + lh + hl.
// cp.async 2-stage double buffer; __launch_bounds__(256,2) for 2 CTAs/SM.
#define KC   32
#define LDT  40
#define TILE_E (128 * LDT)             // elems per tile
#define STAGE_E (4 * TILE_E)           // elems per stage
#define DYN_SMEM (2 * STAGE_E * 2)     // bytes: 2 stages * 4 tiles * 128*LDT bf16

__device__ __forceinline__ void stage_load(
    uint32_t sbase, const __nv_bfloat16* gAh, const __nv_bfloat16* gAl,
    const __nv_bfloat16* gBh, const __nv_bfloat16* gBl, int kc, int tid)
{
    const __nv_bfloat16* srcs[4] = {gAh, gAl, gBh, gBl};
    #pragma unroll
    for (int t = 0; t < 4; t++) {
        #pragma unroll
        for (int it = 0; it < 2; it++) {
            int idx = it * 256 + tid;          // 0..511
            int row = idx >> 2, q = idx & 3;
            uint32_t dst = sbase + (uint32_t)(t * TILE_E + row * LDT + q * 8) * 2;
            const void* src = srcs[t] + (size_t)row * DIM + kc + q * 8;
            CP_ASYNC16(dst, src);
        }
    }
    CP_COMMIT();
}

__global__ __launch_bounds__(256, 2) void k_pairwise()
{
    extern __shared__ __align__(16) __nv_bfloat16 dsm[];
    __shared__ float ssq[128];
    __shared__ int srow[128], scol[128];

    int tid = threadIdx.x, lane = tid & 31, wid = tid >> 5;

    // triangular block mapping
    int id = blockIdx.x;
    int bi = 0, rem = id;
    #pragma unroll 1
    for (int k = 0; k < 32; k++) {
        int rl = 32 - k;
        if (rem < rl) { bi = k; break; }
        rem -= rl;
    }
    int bj = bi + rem;
    const int i0 = bi * 128, j0 = bj * 128;
    const bool diag = (i0 == j0);

    if (tid < 128) {
        srow[tid] = 0x7f800000; scol[tid] = 0x7f800000;
        ssq[tid] = g_sq[j0 + tid];
    }

    const int warpRow = (wid & 3) * 32;
    const int warpCol = (wid >> 2) * 64;

    float c[2][8][4];
    #pragma unroll
    for (int mi = 0; mi < 2; mi++)
        #pragma unroll
        for (int nj = 0; nj < 8; nj++)
            #pragma unroll
            for (int q = 0; q < 4; q++) c[mi][nj][q] = 0.0f;

    int aRow = warpRow + (lane & 7) + ((lane >> 3) & 1) * 8;
    int aCol = (lane >> 4) * 8;
    int bRow = warpCol + (lane & 7) + (lane >> 4) * 8;
    int bCol = ((lane >> 3) & 1) * 8;

    uint32_t dynBase = smem_u32(dsm);

    const __nv_bfloat16* gAh = g_clus_h + (size_t)i0 * DIM;
    const __nv_bfloat16* gAl = g_clus_l + (size_t)i0 * DIM;
    const __nv_bfloat16* gBh = g_clus_h + (size_t)j0 * DIM;
    const __nv_bfloat16* gBl = g_clus_l + (size_t)j0 * DIM;

    const int NK = DIM / KC;   // 16
    stage_load(dynBase, gAh, gAl, gBh, gBl, 0, tid);

    #pragma unroll 1
    for (int kc = 0; kc < NK; kc++) {
        if (kc + 1 < NK)
            stage_load(dynBase + ((kc + 1) & 1) * STAGE_E * 2,
                       gAh, gAl, gBh, gBl, (kc + 1) * KC, tid);
        if (kc + 1 < NK) { CP_WAIT(1); } else { CP_WAIT(0); }
        __syncthreads();

        uint32_t sb = dynBase + (kc & 1) * STAGE_E * 2;
        uint32_t baseAh = sb;
        uint32_t baseAl = sb + TILE_E * 2;
        uint32_t baseBh = sb + 2 * TILE_E * 2;
        uint32_t baseBl = sb + 3 * TILE_E * 2;

        #pragma unroll
        for (int ks = 0; ks < KC; ks += 16) {
            uint32_t ah[2][4], al[2][4], b[4][4];
            #pragma unroll
            for (int mi = 0; mi < 2; mi++) {
                uint32_t addr = baseAh + ((aRow + mi * 16) * LDT + aCol + ks) * 2;
                LDSM_X4(ah[mi][0], ah[mi][1], ah[mi][2], ah[mi][3], addr);
                addr = baseAl + ((aRow + mi * 16) * LDT + aCol + ks) * 2;
                LDSM_X4(al[mi][0], al[mi][1], al[mi][2], al[mi][3], addr);
            }
            #pragma unroll
            for (int pj = 0; pj < 4; pj++) {
                uint32_t addr = baseBh + ((bRow + pj * 16) * LDT + bCol + ks) * 2;
                LDSM_X4(b[pj][0], b[pj][1], b[pj][2], b[pj][3], addr);
            }
            #pragma unroll
            for (int mi = 0; mi < 2; mi++)
                #pragma unroll
                for (int nj = 0; nj < 8; nj++) {
                    int pj = nj >> 1, hh = (nj & 1) * 2;
                    MMA_BF16(c[mi][nj], ah[mi], b[pj][hh], b[pj][hh + 1]);
                    MMA_BF16(c[mi][nj], al[mi], b[pj][hh], b[pj][hh + 1]);
                }
            #pragma unroll
            for (int pj = 0; pj < 4; pj++) {
                uint32_t addr = baseBl + ((bRow + pj * 16) * LDT + bCol + ks) * 2;
                LDSM_X4(b[pj][0], b[pj][1], b[pj][2], b[pj][3], addr);
            }
            #pragma unroll
            for (int mi = 0; mi < 2; mi++)
                #pragma unroll
                for (int nj = 0; nj < 8; nj++) {
                    int pj = nj >> 1, hh = (nj & 1) * 2;
                    MMA_BF16(c[mi][nj], ah[mi], b[pj][hh], b[pj][hh + 1]);
                }
        }
        __syncthreads();
    }

    // epilogue
    int tq = lane >> 2, tr = lane & 3;
    float cmin[8][2];
    #pragma unroll
    for (int nj = 0; nj < 8; nj++) { cmin[nj][0] = 1e30f; cmin[nj][1] = 1e30f; }

    #pragma unroll
    for (int mi = 0; mi < 2; mi++) {
        #pragma unroll
        for (int hr = 0; hr < 2; hr++) {
            int rl = warpRow + mi * 16 + hr * 8 + tq;
            float si = g_sq[i0 + rl];
            float rmin = 1e30f;
            #pragma unroll
            for (int nj = 0; nj < 8; nj++) {
                #pragma unroll
                for (int cc = 0; cc < 2; cc++) {
                    int cl = warpCol + nj * 8 + tr * 2 + cc;
                    float d2 = si + ssq[cl] - 2.0f * c[mi][nj][hr * 2 + cc];
                    float d = sqrtf(fmaxf(d2, EPSF));
                    if (diag && rl == cl) d = 1e30f;
                    rmin = fminf(rmin, d);
                    cmin[nj][cc] = fminf(cmin[nj][cc], d);
                }
            }
            rmin = fminf(rmin, __shfl_xor_sync(0xffffffffu, rmin, 1));
            rmin = fminf(rmin, __shfl_xor_sync(0xffffffffu, rmin, 2));
            if (tr == 0) atomicMin(&srow[rl], __float_as_int(rmin));
        }
    }
    #pragma unroll
    for (int nj = 0; nj < 8; nj++)
        #pragma unroll
        for (int cc = 0; cc < 2; cc++) {
            float v = cmin[nj][cc];
            v = fminf(v, __shfl_xor_sync(0xffffffffu, v, 4));
            v = fminf(v, __shfl_xor_sync(0xffffffffu, v, 8));
            v = fminf(v, __shfl_xor_sync(0xffffffffu, v, 16));
            if (tq == 0)
                atomicMin(&scol[warpCol + nj * 8 + tr * 2 + cc], __float_as_int(v));
        }
    __syncthreads();

    if (tid < 128) {
        atomicMin(&g_rowmin[i0 + tid], srow[tid]);
        atomicMin(&g_rowmin[j0 + tid], scol[tid]);
    }
}

// ---------------- scalar loss reduction --------------------------------------
__global__ __launch_bounds__(1024) void k_reduce()
{
    int tid = threadIdx.x;
    float smin = 0.0f, sin_ = 0.0f, sp = 0.0f;
    for (int i = tid; i < NROWS; i += 1024) {
        smin += __int_as_float(g_rowmin[i]);
        sin_ += g_intra[i];
        sp   += g_par[i];
    }
    #pragma unroll
    for (int o = 16; o > 0; o >>= 1) {
        smin += __shfl_down_sync(0xffffffffu, smin, o);
        sin_ += __shfl_down_sync(0xffffffffu, sin_, o);
        sp   += __shfl_down_sync(0xffffffffu, sp,   o);
    }
    __shared__ float sm[32][3];
    int warp = tid >> 5, lane = tid & 31;
    if (lane == 0) { sm[warp][0] = smin; sm[warp][1] = sin_; sm[warp][2] = sp; }
    __syncthreads();
    if (warp == 0) {
        float a = sm[lane][0], b = sm[lane][1], c = sm[lane][2];
        #pragma unroll
        for (int o = 16; o > 0; o >>= 1) {
            a += __shfl_down_sync(0xffffffffu, a, o);
            b += __shfl_down_sync(0xffffffffu, b, o);
            c += __shfl_down_sync(0xffffffffu, c, o);
        }
        if (lane == 0)
            g_hier = (b - a + c) * (1.0f / (float)NROWS);
    }
}

// ---------------- finalize ----------------------------------------------------
__global__ void k_final(float* __restrict__ out)
{
    int b = blockIdx.x * blockDim.x + threadIdx.x;
    if (b >= BATCH) return;
    float ns = 0.0f;
    const float* p = g_neg + (size_t)b * NEG;
    #pragma unroll
    for (int m = 0; m < NEG; m++) ns += p[m];
    out[b] = -0.5f * g_hier - 0.5f * g_textd[b]
           - GAMMA2_C * (g_true[b] - ns * (1.0f / (float)NEG));
}

// ---------------- launch ------------------------------------------------------
extern "C" void kernel_launch(void* const* d_in, const int* in_sizes, int n_in,
                              void* d_out, int out_size)
{
    const int*   sample   = (const int*)d_in[0];
    const int*   negtails = (const int*)d_in[1];
    const int*   cassign  = (const int*)d_in[2];
    const int*   passign  = (const int*)d_in[3];
    const float* relemb   = (const float*)d_in[4];
    const float* einit    = (const float*)d_in[5];
    const float* etext    = (const float*)d_in[6];
    const float* cemb     = (const float*)d_in[7];
    const float* pemb     = (const float*)d_in[8];
    float* out = (float*)d_out;

    // host-side, idempotent, capture-safe
    cudaFuncSetAttribute(k_pairwise,
                         cudaFuncAttributeMaxDynamicSharedMemorySize, DYN_SMEM);

    k_rows<<<BATCH, 128>>>(sample, cassign, passign, relemb, einit, etext, cemb, pemb);
    k_neg<<<BATCH, 256>>>(negtails, einit, etext);
    k_pairwise<<<528, 256, DYN_SMEM>>>();
    k_reduce<<<1, 1024>>>();
    k_final<<<8, 256>>>(out);
}

// round 7
// speedup vs baseline: 1.7786x; 1.0210x over previous
#include <cuda_runtime.h>
#include <cuda_bf16.h>
#include <cstdint>

#define NENT   200000
#define NRELC  1000
#define DIM    512
#define BATCH  2048
#define NEG    64
#define NROWS  4096
#define EPSF   1e-12f
#define GAMMA_C  12.0f
#define GAMMA2_C 1.0f

// ---------------- scratch ----------------------------------------------------
__device__ __nv_bfloat16 g_clus_h[NROWS * DIM];
__device__ __nv_bfloat16 g_clus_l[NROWS * DIM];
__device__ float g_qh[BATCH * DIM];
__device__ float g_sq[NROWS];
__device__ int   g_rowmin[NROWS];
__device__ float g_intra[NROWS];
__device__ float g_par[NROWS];
__device__ float g_textd[BATCH];
__device__ float g_true[BATCH];
__device__ float g_neg[BATCH * NEG];
__device__ float g_hier;

__device__ __forceinline__ uint32_t smem_u32(const void* p) {
    uint32_t a;
    asm("{ .reg .u64 t; cvta.to.shared.u64 t, %1; cvt.u32.u64 %0, t; }" : "=r"(a) : "l"(p));
    return a;
}

#define LDSM_X4(r0, r1, r2, r3, addr) \
    asm volatile("ldmatrix.sync.aligned.m8n8.x4.shared.b16 {%0,%1,%2,%3}, [%4];" \
        : "=r"(r0), "=r"(r1), "=r"(r2), "=r"(r3) : "r"(addr))

#define MMA_BF16(c, a, b0, b1) \
    asm volatile("mma.sync.aligned.m16n8k16.row.col.f32.bf16.bf16.f32 " \
        "{%0,%1,%2,%3}, {%4,%5,%6,%7}, {%8,%9}, {%0,%1,%2,%3};" \
        : "+f"((c)[0]), "+f"((c)[1]), "+f"((c)[2]), "+f"((c)[3]) \
        : "r"((a)[0]), "r"((a)[1]), "r"((a)[2]), "r"((a)[3]), "r"(b0), "r"(b1))

#define CP_ASYNC16(dst, src) \
    asm volatile("cp.async.cg.shared.global [%0], [%1], 16;" :: "r"(dst), "l"(src))
#define CP_COMMIT() asm volatile("cp.async.commit_group;" ::: "memory")
#define CP_WAIT(n)  asm volatile("cp.async.wait_group %0;" :: "n"(n) : "memory")

// ---------------- per-row gathers + reductions -------------------------------
__device__ __forceinline__ void split_store(int row, int tid, float4 v) {
    union { __nv_bfloat16 b[4]; uint2 u; } uh, ul;
    float xs[4] = {v.x, v.y, v.z, v.w};
    #pragma unroll
    for (int c = 0; c < 4; c++) {
        __nv_bfloat16 h = __float2bfloat16(xs[c]);
        uh.b[c] = h;
        ul.b[c] = __float2bfloat16(xs[c] - __bfloat162float(h));
    }
    *(uint2*)(g_clus_h + (size_t)row * DIM + tid * 4) = uh.u;
    *(uint2*)(g_clus_l + (size_t)row * DIM + tid * 4) = ul.u;
}

__global__ __launch_bounds__(128) void k_rows(
    const int* __restrict__ sample,
    const int* __restrict__ cassign,
    const int* __restrict__ passign,
    const float* __restrict__ relemb,
    const float* __restrict__ einit,
    const float* __restrict__ etext,
    const float* __restrict__ cemb,
    const float* __restrict__ pemb)
{
    int b = blockIdx.x;
    int tid = threadIdx.x;

    if (tid == 0) {
        g_rowmin[b] = 0x7f800000;
        g_rowmin[BATCH + b] = 0x7f800000;
    }

    int h = sample[b * 3 + 0];
    int r = sample[b * 3 + 1] % NRELC;
    int t = sample[b * 3 + 2];
    int hc = cassign[h], tc = cassign[t];
    int hp = passign[hc], tp = passign[tc];

    float4 ih = ((const float4*)(einit + (size_t)h  * DIM))[tid];
    float4 xh = ((const float4*)(etext + (size_t)h  * DIM))[tid];
    float4 it = ((const float4*)(einit + (size_t)t  * DIM))[tid];
    float4 xt = ((const float4*)(etext + (size_t)t  * DIM))[tid];
    float4 rr = ((const float4*)(relemb + (size_t)r * DIM))[tid];
    float4 ch = ((const float4*)(cemb  + (size_t)hc * DIM))[tid];
    float4 ct = ((const float4*)(cemb  + (size_t)tc * DIM))[tid];
    float4 ph = ((const float4*)(pemb  + (size_t)hp * DIM))[tid];
    float4 pt = ((const float4*)(pemb  + (size_t)tp * DIM))[tid];

    float vals[9];
    #pragma unroll
    for (int v = 0; v < 9; v++) vals[v] = 0.0f;

    float4 q4;
    {
        float hi[4] = {ih.x, ih.y, ih.z, ih.w};
        float hx[4] = {xh.x, xh.y, xh.z, xh.w};
        float ti[4] = {it.x, it.y, it.z, it.w};
        float tx2[4] = {xt.x, xt.y, xt.z, xt.w};
        float rv[4] = {rr.x, rr.y, rr.z, rr.w};
        float cv[4] = {ch.x, ch.y, ch.z, ch.w};
        float cw[4] = {ct.x, ct.y, ct.z, ct.w};
        float pv[4] = {ph.x, ph.y, ph.z, ph.w};
        float pw[4] = {pt.x, pt.y, pt.z, pt.w};
        float qv[4];
        #pragma unroll
        for (int c = 0; c < 4; c++) {
            float hcomb = 0.5f * (hi[c] + hx[c]);
            float tcomb = 0.5f * (ti[c] + tx2[c]);
            float q = hcomb + rv[c];
            qv[c] = q;
            vals[0] += fabsf(q - tcomb);
            float dh = 0.5f * (hi[c] - hx[c]);  vals[1] += dh * dh;
            float dt = 0.5f * (ti[c] - tx2[c]); vals[2] += dt * dt;
            float eh = hcomb - cv[c];  vals[3] += eh * eh;
            float et = tcomb - cw[c];  vals[4] += et * et;
            float fh = cv[c] - pv[c];  vals[5] += fh * fh;
            float ft = cw[c] - pw[c];  vals[6] += ft * ft;
            vals[7] += cv[c] * cv[c];
            vals[8] += cw[c] * cw[c];
        }
        q4 = make_float4(qv[0], qv[1], qv[2], qv[3]);
    }

    ((float4*)(g_qh + (size_t)b * DIM))[tid] = q4;
    split_store(b,         tid, ch);
    split_store(BATCH + b, tid, ct);

    #pragma unroll
    for (int o = 16; o > 0; o >>= 1)
        #pragma unroll
        for (int v = 0; v < 9; v++)
            vals[v] += __shfl_down_sync(0xffffffffu, vals[v], o);

    __shared__ float sm[4][9];
    int warp = tid >> 5, lane = tid & 31;
    if (lane == 0) {
        #pragma unroll
        for (int v = 0; v < 9; v++) sm[warp][v] = vals[v];
    }
    __syncthreads();
    if (tid == 0) {
        float s[9];
        #pragma unroll
        for (int v = 0; v < 9; v++)
            s[v] = sm[0][v] + sm[1][v] + sm[2][v] + sm[3][v];
        g_true[b]          = GAMMA_C - s[0];
        g_textd[b]         = sqrtf(s[1] + EPSF) + sqrtf(s[2] + EPSF);
        g_intra[b]         = sqrtf(s[3] + EPSF);
        g_intra[BATCH + b] = sqrtf(s[4] + EPSF);
        g_par[b]           = sqrtf(s[5] + EPSF);
        g_par[BATCH + b]   = sqrtf(s[6] + EPSF);
        g_sq[b]            = s[7];
        g_sq[BATCH + b]    = s[8];
    }
}

// ---------------- negative-sample L1 scores ----------------------------------
__global__ __launch_bounds__(256) void k_neg(
    const int* __restrict__ negtails,
    const float* __restrict__ einit,
    const float* __restrict__ etext)
{
    int b = blockIdx.x;
    int tid = threadIdx.x;
    __shared__ __align__(16) float qs[DIM];

    ((float2*)qs)[tid] = ((const float2*)(g_qh + (size_t)b * DIM))[tid];
    __syncthreads();

    int w = tid >> 5, lane = tid & 31;
    const float4* qv = (const float4*)qs;

    #pragma unroll 1
    for (int mm = 0; mm < 8; mm++) {
        int m = w * 8 + mm;
        int e = negtails[b * NEG + m];
        const float4* av = (const float4*)(einit + (size_t)e * DIM);
        const float4* xv = (const float4*)(etext + (size_t)e * DIM);
        float s = 0.0f;
        #pragma unroll
        for (int i = 0; i < 4; i++) {
            int idx = i * 32 + lane;
            float4 a = __ldg(av + idx);
            float4 x = __ldg(xv + idx);
            float4 q = qv[idx];
            s += fabsf(q.x - 0.5f * (a.x + x.x))
               + fabsf(q.y - 0.5f * (a.y + x.y))
               + fabsf(q.z - 0.5f * (a.z + x.z))
               + fabsf(q.w - 0.5f * (a.w + x.w));
        }
        #pragma unroll
        for (int o = 16; o > 0; o >>= 1)
            s += __shfl_down_sync(0xffffffffu, s, o);
        if (lane == 0)
            g_neg[b * NEG + m] = GAMMA_C - s;
    }
}

// ---------------- mma.sync pairwise-L2 row minima ----------------------------
#define KC   32
#define LDT  40
#define TILE_E (128 * LDT)
#define STAGE_E (4 * TILE_E)
#define DYN_SMEM (2 * STAGE_E * 2)

__device__ __forceinline__ void stage_load(
    uint32_t sbase, const __nv_bfloat16* gAh, const __nv_bfloat16* gAl,
    const __nv_bfloat16* gBh, const __nv_bfloat16* gBl, int kc, int tid)
{
    const __nv_bfloat16* srcs[4] = {gAh, gAl, gBh, gBl};
    #pragma unroll
    for (int t = 0; t < 4; t++) {
        #pragma unroll
        for (int it = 0; it < 2; it++) {
            int idx = it * 256 + tid;
            int row = idx >> 2, q = idx & 3;
            uint32_t dst = sbase + (uint32_t)(t * TILE_E + row * LDT + q * 8) * 2;
            const void* src = srcs[t] + (size_t)row * DIM + kc + q * 8;
            CP_ASYNC16(dst, src);
        }
    }
    CP_COMMIT();
}

__global__ __launch_bounds__(256, 2) void k_pairwise()
{
    extern __shared__ __align__(16) __nv_bfloat16 dsm[];
    __shared__ float ssq[128];
    __shared__ int srow[128], scol[128];

    int tid = threadIdx.x, lane = tid & 31, wid = tid >> 5;

    int id = blockIdx.x;
    int bi = 0, rem = id;
    #pragma unroll 1
    for (int k = 0; k < 32; k++) {
        int rl = 32 - k;
        if (rem < rl) { bi = k; break; }
        rem -= rl;
    }
    int bj = bi + rem;
    const int i0 = bi * 128, j0 = bj * 128;
    const bool diag = (i0 == j0);

    if (tid < 128) {
        srow[tid] = 0x7f800000; scol[tid] = 0x7f800000;
        ssq[tid] = g_sq[j0 + tid];
    }

    const int warpRow = (wid & 3) * 32;
    const int warpCol = (wid >> 2) * 64;

    float c[2][8][4];
    #pragma unroll
    for (int mi = 0; mi < 2; mi++)
        #pragma unroll
        for (int nj = 0; nj < 8; nj++)
            #pragma unroll
            for (int q = 0; q < 4; q++) c[mi][nj][q] = 0.0f;

    int aRow = warpRow + (lane & 7) + ((lane >> 3) & 1) * 8;
    int aCol = (lane >> 4) * 8;
    int bRow = warpCol + (lane & 7) + (lane >> 4) * 8;
    int bCol = ((lane >> 3) & 1) * 8;

    uint32_t dynBase = smem_u32(dsm);

    const __nv_bfloat16* gAh = g_clus_h + (size_t)i0 * DIM;
    const __nv_bfloat16* gAl = g_clus_l + (size_t)i0 * DIM;
    const __nv_bfloat16* gBh = g_clus_h + (size_t)j0 * DIM;
    const __nv_bfloat16* gBl = g_clus_l + (size_t)j0 * DIM;

    const int NK = DIM / KC;
    stage_load(dynBase, gAh, gAl, gBh, gBl, 0, tid);

    #pragma unroll 1
    for (int kc = 0; kc < NK; kc++) {
        if (kc + 1 < NK)
            stage_load(dynBase + ((kc + 1) & 1) * STAGE_E * 2,
                       gAh, gAl, gBh, gBl, (kc + 1) * KC, tid);
        if (kc + 1 < NK) { CP_WAIT(1); } else { CP_WAIT(0); }
        __syncthreads();

        uint32_t sb = dynBase + (kc & 1) * STAGE_E * 2;
        uint32_t baseAh = sb;
        uint32_t baseAl = sb + TILE_E * 2;
        uint32_t baseBh = sb + 2 * TILE_E * 2;
        uint32_t baseBl = sb + 3 * TILE_E * 2;

        #pragma unroll
        for (int ks = 0; ks < KC; ks += 16) {
            uint32_t ah[2][4], al[2][4], b[4][4];
            #pragma unroll
            for (int mi = 0; mi < 2; mi++) {
                uint32_t addr = baseAh + ((aRow + mi * 16) * LDT + aCol + ks) * 2;
                LDSM_X4(ah[mi][0], ah[mi][1], ah[mi][2], ah[mi][3], addr);
                addr = baseAl + ((aRow + mi * 16) * LDT + aCol + ks) * 2;
                LDSM_X4(al[mi][0], al[mi][1], al[mi][2], al[mi][3], addr);
            }
            #pragma unroll
            for (int pj = 0; pj < 4; pj++) {
                uint32_t addr = baseBh + ((bRow + pj * 16) * LDT + bCol + ks) * 2;
                LDSM_X4(b[pj][0], b[pj][1], b[pj][2], b[pj][3], addr);
            }
            #pragma unroll
            for (int mi = 0; mi < 2; mi++)
                #pragma unroll
                for (int nj = 0; nj < 8; nj++) {
                    int pj = nj >> 1, hh = (nj & 1) * 2;
                    MMA_BF16(c[mi][nj], ah[mi], b[pj][hh], b[pj][hh + 1]);
                    MMA_BF16(c[mi][nj], al[mi], b[pj][hh], b[pj][hh + 1]);
                }
            #pragma unroll
            for (int pj = 0; pj < 4; pj++) {
                uint32_t addr = baseBl + ((bRow + pj * 16) * LDT + bCol + ks) * 2;
                LDSM_X4(b[pj][0], b[pj][1], b[pj][2], b[pj][3], addr);
            }
            #pragma unroll
            for (int mi = 0; mi < 2; mi++)
                #pragma unroll
                for (int nj = 0; nj < 8; nj++) {
                    int pj = nj >> 1, hh = (nj & 1) * 2;
                    MMA_BF16(c[mi][nj], ah[mi], b[pj][hh], b[pj][hh + 1]);
                }
        }
        __syncthreads();
    }

    // epilogue
    int tq = lane >> 2, tr = lane & 3;
    float cmin[8][2];
    #pragma unroll
    for (int nj = 0; nj < 8; nj++) { cmin[nj][0] = 1e30f; cmin[nj][1] = 1e30f; }

    #pragma unroll
    for (int mi = 0; mi < 2; mi++) {
        #pragma unroll
        for (int hr = 0; hr < 2; hr++) {
            int rl = warpRow + mi * 16 + hr * 8 + tq;
            float si = g_sq[i0 + rl];
            float rmin = 1e30f;
            #pragma unroll
            for (int nj = 0; nj < 8; nj++) {
                #pragma unroll
                for (int cc = 0; cc < 2; cc++) {
                    int cl = warpCol + nj * 8 + tr * 2 + cc;
                    float d2 = si + ssq[cl] - 2.0f * c[mi][nj][hr * 2 + cc];
                    float d = sqrtf(fmaxf(d2, EPSF));
                    if (diag && rl == cl) d = 1e30f;
                    rmin = fminf(rmin, d);
                    cmin[nj][cc] = fminf(cmin[nj][cc], d);
                }
            }
            rmin = fminf(rmin, __shfl_xor_sync(0xffffffffu, rmin, 1));
            rmin = fminf(rmin, __shfl_xor_sync(0xffffffffu, rmin, 2));
            if (tr == 0) atomicMin(&srow[rl], __float_as_int(rmin));
        }
    }
    #pragma unroll
    for (int nj = 0; nj < 8; nj++)
        #pragma unroll
        for (int cc = 0; cc < 2; cc++) {
            float v = cmin[nj][cc];
            v = fminf(v, __shfl_xor_sync(0xffffffffu, v, 4));
            v = fminf(v, __shfl_xor_sync(0xffffffffu, v, 8));
            v = fminf(v, __shfl_xor_sync(0xffffffffu, v, 16));
            if (tq == 0)
                atomicMin(&scol[warpCol + nj * 8 + tr * 2 + cc], __float_as_int(v));
        }
    __syncthreads();

    if (tid < 128) {
        atomicMin(&g_rowmin[i0 + tid], srow[tid]);
        atomicMin(&g_rowmin[j0 + tid], scol[tid]);
    }
}

// ---------------- scalar loss reduction --------------------------------------
__global__ __launch_bounds__(1024) void k_reduce()
{
    int tid = threadIdx.x;
    float smin = 0.0f, sin_ = 0.0f, sp = 0.0f;
    for (int i = tid; i < NROWS; i += 1024) {
        smin += __int_as_float(g_rowmin[i]);
        sin_ += g_intra[i];
        sp   += g_par[i];
    }
    #pragma unroll
    for (int o = 16; o > 0; o >>= 1) {
        smin += __shfl_down_sync(0xffffffffu, smin, o);
        sin_ += __shfl_down_sync(0xffffffffu, sin_, o);
        sp   += __shfl_down_sync(0xffffffffu, sp,   o);
    }
    __shared__ float sm[32][3];
    int warp = tid >> 5, lane = tid & 31;
    if (lane == 0) { sm[warp][0] = smin; sm[warp][1] = sin_; sm[warp][2] = sp; }
    __syncthreads();
    if (warp == 0) {
        float a = sm[lane][0], b = sm[lane][1], c = sm[lane][2];
        #pragma unroll
        for (int o = 16; o > 0; o >>= 1) {
            a += __shfl_down_sync(0xffffffffu, a, o);
            b += __shfl_down_sync(0xffffffffu, b, o);
            c += __shfl_down_sync(0xffffffffu, c, o);
        }
        if (lane == 0)
            g_hier = (b - a + c) * (1.0f / (float)NROWS);
    }
}

// ---------------- finalize ----------------------------------------------------
__global__ void k_final(float* __restrict__ out)
{
    int b = blockIdx.x * blockDim.x + threadIdx.x;
    if (b >= BATCH) return;
    float ns = 0.0f;
    const float* p = g_neg + (size_t)b * NEG;
    #pragma unroll
    for (int m = 0; m < NEG; m++) ns += p[m];
    out[b] = -0.5f * g_hier - 0.5f * g_textd[b]
           - GAMMA2_C * (g_true[b] - ns * (1.0f / (float)NEG));
}

// ---------------- launch ------------------------------------------------------
// Fork-join: after k_rows, k_neg runs on a side stream concurrently with
// k_pairwise+k_reduce on the main stream; join before k_final. Streams/events
// are created fresh each call (host-side only, no device memory) and
// intentionally not destroyed: destroying a stream that participates in an
// active capture is illegal, and kernel_launch is only invoked a bounded
// number of times (correctness + capture).
extern "C" void kernel_launch(void* const* d_in, const int* in_sizes, int n_in,
                              void* d_out, int out_size)
{
    const int*   sample   = (const int*)d_in[0];
    const int*   negtails = (const int*)d_in[1];
    const int*   cassign  = (const int*)d_in[2];
    const int*   passign  = (const int*)d_in[3];
    const float* relemb   = (const float*)d_in[4];
    const float* einit    = (const float*)d_in[5];
    const float* etext    = (const float*)d_in[6];
    const float* cemb     = (const float*)d_in[7];
    const float* pemb     = (const float*)d_in[8];
    float* out = (float*)d_out;

    cudaFuncSetAttribute(k_pairwise,
                         cudaFuncAttributeMaxDynamicSharedMemorySize, DYN_SMEM);

    cudaStream_t side;
    cudaEvent_t evFork, evJoin;
    cudaStreamCreateWithFlags(&side, cudaStreamNonBlocking);
    cudaEventCreateWithFlags(&evFork, cudaEventDisableTiming);
    cudaEventCreateWithFlags(&evJoin, cudaEventDisableTiming);

    k_rows<<<BATCH, 128>>>(sample, cassign, passign, relemb, einit, etext, cemb, pemb);

    // fork: side stream waits on k_rows
    cudaEventRecord(evFork, 0);
    cudaStreamWaitEvent(side, evFork, 0);

    // branch A (side): negative scores (DRAM-bound)
    k_neg<<<BATCH, 256, 0, side>>>(negtails, einit, etext);
    cudaEventRecord(evJoin, side);

    // branch B (main): pairwise Gram (tensor-bound) + scalar reduce
    k_pairwise<<<528, 256, DYN_SMEM>>>();
    k_reduce<<<1, 1024>>>();

    // join: main waits on k_neg before finalize
    cudaStreamWaitEvent(0, evJoin, 0);
    k_final<<<8, 256>>>(out);
}